// round 3
// baseline (speedup 1.0000x reference)
#include <cuda_runtime.h>
#include <math.h>

#define NMAT 4
#define NSUB 4096
#define DIM 64
#define KTOP 20
#define NROWS 8192
#define NSEG 8
#define SEGCOLS 1024

// scratch (device globals: no allocation allowed)
__device__ float g_v1[NMAT][NSUB][DIM];
__device__ float g_v2[NMAT][NSUB][DIM];
__device__ float g_pval[NROWS][NSEG][KTOP];
__device__ int   g_pcol[NROWS][NSEG][KTOP];

// ---------------------------------------------------------------------------
// Zero the 256MB output (poisoned with 0xAA by harness)
// ---------------------------------------------------------------------------
__global__ void zero_kernel(float4* out, int n4) {
    int stride = gridDim.x * blockDim.x;
    for (int t = blockIdx.x * blockDim.x + threadIdx.x; t < n4; t += stride)
        out[t] = make_float4(0.f, 0.f, 0.f, 0.f);
}

// ---------------------------------------------------------------------------
// v = emb @ w + b, per block k. grid = (row_tile 64, k=4, which=2), 256 thr.
// ---------------------------------------------------------------------------
__global__ void compute_v_kernel(const float* __restrict__ emb1,
                                 const float* __restrict__ emb2,
                                 const float* __restrict__ w1,
                                 const float* __restrict__ w2,
                                 const float* __restrict__ b1,
                                 const float* __restrict__ b2) {
    int which = blockIdx.z;
    int k = blockIdx.y;
    int tile = blockIdx.x;
    const float* emb = which ? emb2 : emb1;
    const float* w   = which ? w2   : w1;
    const float* b   = which ? b2   : b1;
    float* vout      = which ? &g_v2[0][0][0] : &g_v1[0][0][0];

    __shared__ float semb[64 * 65];   // padded rows
    __shared__ float sw[64 * 64];
    __shared__ float sb[64];

    int tid = threadIdx.x;
    for (int t = tid; t < 4096; t += 256) {
        int r = t >> 6, e = t & 63;
        semb[r * 65 + e] = emb[(size_t)(k * NSUB + tile * 64 + r) * 64 + e];
        sw[t] = w[k * 4096 + t];
    }
    if (tid < 64) sb[tid] = b[k * 64 + tid];
    __syncthreads();

    int nl = tid & 63, q = tid >> 6;
    float acc[16];
#pragma unroll
    for (int d = 0; d < 16; d++) acc[d] = 0.f;

#pragma unroll 4
    for (int e = 0; e < 64; e++) {
        float a = semb[nl * 65 + e];
#pragma unroll
        for (int jj = 0; jj < 4; jj++) {
            float4 wv = *(const float4*)&sw[e * 64 + q * 16 + jj * 4];
            acc[jj * 4 + 0] += a * wv.x;
            acc[jj * 4 + 1] += a * wv.y;
            acc[jj * 4 + 2] += a * wv.z;
            acc[jj * 4 + 3] += a * wv.w;
        }
    }

    float* orow = &vout[(size_t)(k * NSUB + tile * 64 + nl) * 64];
#pragma unroll
    for (int dd = 0; dd < 16; dd++) {
        int d = q * 16 + dd;
        orow[d] = acc[dd] + sb[d];
    }
}

// ---------------------------------------------------------------------------
// Scores + per-segment streaming top-20.
// grid = (segment s: 8, row-tile rt: 128), 256 threads.
// Each CTA: 64 rows (module-local (rt&63)*64) x 1024 cols, 16 chunks of 64.
// ---------------------------------------------------------------------------
__global__ void score_topk_kernel() {
    int s   = blockIdx.x;             // segment 0..7
    int rt  = blockIdx.y;             // row tile 0..127
    int tid = threadIdx.x;
    int i = rt >> 6;                  // module of rows
    int j = s >> 2;                   // module of cols
    int k = i * 2 + j;                // block index
    int rowbase = rt * 64;            // GLOBAL row base (for output scratch)
    int nloc = (rt & 63) * 64;        // MODULE-LOCAL row base (for g_v1)  <-- fix
    int mbase = (s & 3) * SEGCOLS;    // module-local col offset

    __shared__ float sv1[64 * 68];    // [e][row], padded stride 68
    __shared__ float sv2[64 * 68];    // [e][col], then reused as scores [row][col]
    __shared__ float stkv[64 * KTOP];
    __shared__ int   stkc[64 * KTOP];

    for (int t = tid; t < 4096; t += 256) {
        int r = t >> 6, e = t & 63;
        sv1[e * 68 + r] = g_v1[k][nloc + r][e];
    }
    for (int t = tid; t < 64 * KTOP; t += 256) { stkv[t] = -1e30f; stkc[t] = 0; }
    float minv = -1e30f;
    int tx = tid & 15, ty = tid >> 4;
    __syncthreads();

    for (int cc = 0; cc < 16; cc++) {
        // load v2 chunk (64 module-local cols) transposed
        for (int t = tid; t < 4096; t += 256) {
            int c = t >> 6, e = t & 63;
            sv2[e * 68 + c] = g_v2[k][mbase + cc * 64 + c][e];
        }
        __syncthreads();

        float acc[4][4];
#pragma unroll
        for (int a2 = 0; a2 < 4; a2++)
#pragma unroll
            for (int b2 = 0; b2 < 4; b2++) acc[a2][b2] = 0.f;

#pragma unroll 4
        for (int e = 0; e < 64; e++) {
            float4 av = *(const float4*)&sv1[e * 68 + ty * 4];
            float4 bv = *(const float4*)&sv2[e * 68 + tx * 4];
            acc[0][0] += av.x * bv.x; acc[0][1] += av.x * bv.y;
            acc[0][2] += av.x * bv.z; acc[0][3] += av.x * bv.w;
            acc[1][0] += av.y * bv.x; acc[1][1] += av.y * bv.y;
            acc[1][2] += av.y * bv.z; acc[1][3] += av.y * bv.w;
            acc[2][0] += av.z * bv.x; acc[2][1] += av.z * bv.y;
            acc[2][2] += av.z * bv.z; acc[2][3] += av.z * bv.w;
            acc[3][0] += av.w * bv.x; acc[3][1] += av.w * bv.y;
            acc[3][2] += av.w * bv.z; acc[3][3] += av.w * bv.w;
        }
        __syncthreads();   // all reads of sv2 done before overwriting with scores

        // stage scores: sv2[row*68 + col]
#pragma unroll
        for (int rr = 0; rr < 4; rr++) {
            float4 svv = make_float4(acc[rr][0], acc[rr][1], acc[rr][2], acc[rr][3]);
            *(float4*)&sv2[(ty * 4 + rr) * 68 + tx * 4] = svv;
        }
        __syncthreads();

        // drain: one thread per row updates its sorted-ascending top-20
        if (tid < 64) {
            int colg = s * SEGCOLS + cc * 64;   // global column base
            const float* row = &sv2[tid * 68];
            float* kvv = &stkv[tid * KTOP];
            int*   kcc = &stkc[tid * KTOP];
            for (int c = 0; c < 64; c++) {
                float v = row[c];
                if (v > minv) {
                    int p = 0;
                    while (p < KTOP - 1 && kvv[p + 1] < v) {
                        kvv[p] = kvv[p + 1]; kcc[p] = kcc[p + 1]; p++;
                    }
                    kvv[p] = v; kcc[p] = colg + c;
                    minv = kvv[0];
                }
            }
        }
        __syncthreads();
    }

    // write per-segment partial top-20 to scratch
    for (int t = tid; t < 64 * KTOP; t += 256) {
        int r = t / KTOP, p = t % KTOP;
        g_pval[rowbase + r][s][p] = stkv[t];
        g_pcol[rowbase + r][s][p] = stkc[t];
    }
}

// ---------------------------------------------------------------------------
// Merge 8 segment-partials per row -> global top-20, scatter relu(tanh(3a)).
// ---------------------------------------------------------------------------
__global__ void merge_kernel(float* __restrict__ out) {
    int r = blockIdx.x * blockDim.x + threadIdx.x;
    if (r >= NROWS) return;
    float tv[KTOP]; int tc[KTOP];
#pragma unroll
    for (int p = 0; p < KTOP; p++) { tv[p] = -1e30f; tc[p] = 0; }

    for (int s = 0; s < NSEG; s++) {
        for (int t = 0; t < KTOP; t++) {
            float v = g_pval[r][s][t];
            int   c = g_pcol[r][s][t];
            if (v > tv[0]) {
                int p = 0;
                while (p < KTOP - 1 && tv[p + 1] < v) {
                    tv[p] = tv[p + 1]; tc[p] = tc[p + 1]; p++;
                }
                tv[p] = v; tc[p] = c;
            }
        }
    }

    float* orow = out + (size_t)r * NROWS;
#pragma unroll
    for (int p = 0; p < KTOP; p++) {
        float a = tv[p];
        if (a > -1e29f) {
            orow[tc[p]] = (a > 0.f) ? tanhf(3.0f * a) : 0.f;
        }
    }
}

// ---------------------------------------------------------------------------
extern "C" void kernel_launch(void* const* d_in, const int* in_sizes, int n_in,
                              void* d_out, int out_size) {
    // inputs: idx, emb1, emb2, w1, w2, b1, b2
    const float* emb1 = (const float*)d_in[1];
    const float* emb2 = (const float*)d_in[2];
    const float* w1   = (const float*)d_in[3];
    const float* w2   = (const float*)d_in[4];
    const float* b1   = (const float*)d_in[5];
    const float* b2   = (const float*)d_in[6];
    float* out = (float*)d_out;

    zero_kernel<<<8192, 256>>>((float4*)out, out_size / 4);
    compute_v_kernel<<<dim3(64, NMAT, 2), 256>>>(emb1, emb2, w1, w2, b1, b2);
    score_topk_kernel<<<dim3(NSEG, 128), 256>>>();
    merge_kernel<<<NROWS / 256, 256>>>(out);
}

// round 4
// speedup vs baseline: 1.8432x; 1.8432x over previous
#include <cuda_runtime.h>
#include <math.h>

#define NMAT 4
#define NSUB 4096
#define DIM 64
#define KTOP 20
#define NROWS 8192
#define NSEG 8
#define SEGCOLS 1024

// scratch (device globals: no allocation allowed)
__device__ float g_v1[NMAT][NSUB][DIM];
__device__ float g_v2[NMAT][NSUB][DIM];
__device__ float g_pval[NROWS][NSEG][KTOP];
__device__ int   g_pcol[NROWS][NSEG][KTOP];

// ---------------------------------------------------------------------------
// Zero the 256MB output (poisoned with 0xAA by harness)
// ---------------------------------------------------------------------------
__global__ void zero_kernel(float4* out, int n4) {
    int stride = gridDim.x * blockDim.x;
    for (int t = blockIdx.x * blockDim.x + threadIdx.x; t < n4; t += stride)
        out[t] = make_float4(0.f, 0.f, 0.f, 0.f);
}

// ---------------------------------------------------------------------------
// v = emb @ w + b, per block k. grid = (row_tile 64, k=4, which=2), 256 thr.
// ---------------------------------------------------------------------------
__global__ void compute_v_kernel(const float* __restrict__ emb1,
                                 const float* __restrict__ emb2,
                                 const float* __restrict__ w1,
                                 const float* __restrict__ w2,
                                 const float* __restrict__ b1,
                                 const float* __restrict__ b2) {
    int which = blockIdx.z;
    int k = blockIdx.y;
    int tile = blockIdx.x;
    const float* emb = which ? emb2 : emb1;
    const float* w   = which ? w2   : w1;
    const float* b   = which ? b2   : b1;
    float* vout      = which ? &g_v2[0][0][0] : &g_v1[0][0][0];

    __shared__ float semb[64 * 65];
    __shared__ float sw[64 * 64];
    __shared__ float sb[64];

    int tid = threadIdx.x;
    for (int t = tid; t < 4096; t += 256) {
        int r = t >> 6, e = t & 63;
        semb[r * 65 + e] = emb[(size_t)(k * NSUB + tile * 64 + r) * 64 + e];
        sw[t] = w[k * 4096 + t];
    }
    if (tid < 64) sb[tid] = b[k * 64 + tid];
    __syncthreads();

    int nl = tid & 63, q = tid >> 6;
    float acc[16];
#pragma unroll
    for (int d = 0; d < 16; d++) acc[d] = 0.f;

#pragma unroll 4
    for (int e = 0; e < 64; e++) {
        float a = semb[nl * 65 + e];
#pragma unroll
        for (int jj = 0; jj < 4; jj++) {
            float4 wv = *(const float4*)&sw[e * 64 + q * 16 + jj * 4];
            acc[jj * 4 + 0] += a * wv.x;
            acc[jj * 4 + 1] += a * wv.y;
            acc[jj * 4 + 2] += a * wv.z;
            acc[jj * 4 + 3] += a * wv.w;
        }
    }

    float* orow = &vout[(size_t)(k * NSUB + tile * 64 + nl) * 64];
#pragma unroll
    for (int dd = 0; dd < 16; dd++) {
        int d = q * 16 + dd;
        orow[d] = acc[dd] + sb[d];
    }
}

// ---------------------------------------------------------------------------
// Scores + per-segment streaming top-20, threshold-filtered FIFO version.
// grid = (segment s: 8, row-tile rt: 128), 256 threads, 87.5KB dyn smem.
// Per chunk: compute 64x64 scores in-register, append only those above the
// row's lazy 20th-best to a per-row FIFO; drain (2 warps) overlaps with the
// next chunk's v2 load (6 warps, double-buffered).
// ---------------------------------------------------------------------------
__global__ void score_topk_kernel() {
    extern __shared__ float dsm[];
    float* sv1     = dsm;                       // [e][row]  64*68
    float* sv2     = dsm + 4352;                // 2 bufs of [e][col] 64*68
    float* cval    = dsm + 4352 * 3;            // [row][64] FIFO values
    float* kvv     = cval + 4096;               // [row][20] sorted ascending
    int*   kcc     = (int*)(kvv + 64 * KTOP);   // [row][20]
    short* ccol    = (short*)(kcc + 64 * KTOP); // [row][64] FIFO local cols
    int*   ccnt    = (int*)(ccol + 4096);       // [row]
    float* srowmin = (float*)(ccnt + 64);       // [row]

    int s   = blockIdx.x;
    int rt  = blockIdx.y;
    int tid = threadIdx.x;
    int i = rt >> 6;
    int j = s >> 2;
    int k = i * 2 + j;
    int rowbase = rt * 64;            // global rows (scratch out)
    int nloc = (rt & 63) * 64;        // module-local rows (g_v1)
    int mbase = (s & 3) * SEGCOLS;    // module-local col offset

    // init
    for (int t = tid; t < 4096; t += 256) {
        int r = t >> 6, e = t & 63;
        sv1[e * 68 + r] = g_v1[k][nloc + r][e];
        sv2[e * 68 + r] = g_v2[k][mbase + r][e];   // chunk 0 into buf 0 (r==c)
    }
    for (int t = tid; t < 64 * KTOP; t += 256) { kvv[t] = -1e30f; kcc[t] = 0; }
    if (tid < 64) { ccnt[tid] = 0; srowmin[tid] = -1e30f; }
    int tx = tid & 15, ty = tid >> 4;
    __syncthreads();

    for (int cc = 0; cc < 16; cc++) {
        const float* v2b = sv2 + (cc & 1) * 4352;

        float acc[4][4];
#pragma unroll
        for (int a2 = 0; a2 < 4; a2++)
#pragma unroll
            for (int b2 = 0; b2 < 4; b2++) acc[a2][b2] = 0.f;

#pragma unroll 4
        for (int e = 0; e < 64; e++) {
            float4 av = *(const float4*)&sv1[e * 68 + ty * 4];
            float4 bv = *(const float4*)&v2b[e * 68 + tx * 4];
            acc[0][0] += av.x * bv.x; acc[0][1] += av.x * bv.y;
            acc[0][2] += av.x * bv.z; acc[0][3] += av.x * bv.w;
            acc[1][0] += av.y * bv.x; acc[1][1] += av.y * bv.y;
            acc[1][2] += av.y * bv.z; acc[1][3] += av.y * bv.w;
            acc[2][0] += av.z * bv.x; acc[2][1] += av.z * bv.y;
            acc[2][2] += av.z * bv.z; acc[2][3] += av.z * bv.w;
            acc[3][0] += av.w * bv.x; acc[3][1] += av.w * bv.y;
            acc[3][2] += av.w * bv.z; acc[3][3] += av.w * bv.w;
        }

        // threshold filter + FIFO append (per row; <=64 appends/row/chunk)
#pragma unroll
        for (int rr = 0; rr < 4; rr++) {
            int r = ty * 4 + rr;
            float rmin = srowmin[r];
            int n = (acc[rr][0] > rmin) + (acc[rr][1] > rmin) +
                    (acc[rr][2] > rmin) + (acc[rr][3] > rmin);
            if (n) {
                int p = atomicAdd(&ccnt[r], n);
                if (acc[rr][0] > rmin) { cval[r*64+p] = acc[rr][0]; ccol[r*64+p] = (short)(tx*4+0); p++; }
                if (acc[rr][1] > rmin) { cval[r*64+p] = acc[rr][1]; ccol[r*64+p] = (short)(tx*4+1); p++; }
                if (acc[rr][2] > rmin) { cval[r*64+p] = acc[rr][2]; ccol[r*64+p] = (short)(tx*4+2); p++; }
                if (acc[rr][3] > rmin) { cval[r*64+p] = acc[rr][3]; ccol[r*64+p] = (short)(tx*4+3); }
            }
        }
        __syncthreads();

        // drain (warps 0-1) overlapped with next-chunk v2 load (warps 2-7)
        if (tid < 64) {
            int r = tid;
            int n = ccnt[r];
            float* kv = &kvv[r * KTOP];
            int*   kc = &kcc[r * KTOP];
            float minv = kv[0];
            int colg = s * SEGCOLS + cc * 64;
            for (int q = 0; q < n; q++) {
                float v = cval[r * 64 + q];
                if (v > minv) {
                    int col = colg + (int)ccol[r * 64 + q];
                    int p = 0;
                    while (p < KTOP - 1 && kv[p + 1] < v) {
                        kv[p] = kv[p + 1]; kc[p] = kc[p + 1]; p++;
                    }
                    kv[p] = v; kc[p] = col;
                    minv = kv[0];
                }
            }
            ccnt[r] = 0;
            srowmin[r] = minv;
        } else if (cc + 1 < 16) {
            float* nb = sv2 + ((cc + 1) & 1) * 4352;
            for (int t = tid - 64; t < 4096; t += 192) {
                int c = t >> 6, e = t & 63;
                nb[e * 68 + c] = g_v2[k][mbase + (cc + 1) * 64 + c][e];
            }
        }
        __syncthreads();
    }

    // write per-segment partial top-20 to scratch
    for (int t = tid; t < 64 * KTOP; t += 256) {
        int r = t / KTOP, p = t % KTOP;
        g_pval[rowbase + r][s][p] = kvv[t];
        g_pcol[rowbase + r][s][p] = kcc[t];
    }
}

// ---------------------------------------------------------------------------
// Merge: warp per row. 160 candidates -> 20 rounds of butterfly argmax.
// All candidate state in named scalars (no local-memory arrays).
// ---------------------------------------------------------------------------
__global__ void merge_kernel(float* __restrict__ out) {
    int warp = threadIdx.x >> 5;
    int lane = threadIdx.x & 31;
    int row = blockIdx.x * 8 + warp;
    if (row >= NROWS) return;

    const float* pv = &g_pval[row][0][0];   // 160 contiguous
    const int*   pc = &g_pcol[row][0][0];

    float v0 = pv[lane * 5 + 0], v1 = pv[lane * 5 + 1], v2 = pv[lane * 5 + 2],
          v3 = pv[lane * 5 + 3], v4 = pv[lane * 5 + 4];
    int   c0 = pc[lane * 5 + 0], c1 = pc[lane * 5 + 1], c2 = pc[lane * 5 + 2],
          c3 = pc[lane * 5 + 3], c4 = pc[lane * 5 + 4];

    float outv = 0.f; int outc = -1;

#pragma unroll
    for (int kk = 0; kk < KTOP; kk++) {
        // local argmax over 5 slots
        float bv = v0; int bs = 0;
        if (v1 > bv) { bv = v1; bs = 1; }
        if (v2 > bv) { bv = v2; bs = 2; }
        if (v3 > bv) { bv = v3; bs = 3; }
        if (v4 > bv) { bv = v4; bs = 4; }
        int bc = (bs == 0) ? c0 : (bs == 1) ? c1 : (bs == 2) ? c2 : (bs == 3) ? c3 : c4;
        int bi = lane * 8 + bs;   // owner encoding

        // butterfly argmax reduce (ties -> lower idx), all lanes converge
#pragma unroll
        for (int off = 16; off > 0; off >>= 1) {
            float ov = __shfl_xor_sync(0xffffffffu, bv, off);
            int   oc = __shfl_xor_sync(0xffffffffu, bc, off);
            int   oi = __shfl_xor_sync(0xffffffffu, bi, off);
            if (ov > bv || (ov == bv && oi < bi)) { bv = ov; bc = oc; bi = oi; }
        }

        // remove winner from owner lane
        if (lane == (bi >> 3)) {
            int ws = bi & 7;
            if      (ws == 0) v0 = -1e30f;
            else if (ws == 1) v1 = -1e30f;
            else if (ws == 2) v2 = -1e30f;
            else if (ws == 3) v3 = -1e30f;
            else              v4 = -1e30f;
        }
        if (lane == kk) { outv = bv; outc = bc; }
    }

    if (lane < KTOP) {
        float t = (outv > 0.f) ? tanhf(3.0f * outv) : 0.f;
        out[(size_t)row * NROWS + outc] = t;
    }
}

// ---------------------------------------------------------------------------
extern "C" void kernel_launch(void* const* d_in, const int* in_sizes, int n_in,
                              void* d_out, int out_size) {
    // inputs: idx, emb1, emb2, w1, w2, b1, b2
    const float* emb1 = (const float*)d_in[1];
    const float* emb2 = (const float*)d_in[2];
    const float* w1   = (const float*)d_in[3];
    const float* w2   = (const float*)d_in[4];
    const float* b1   = (const float*)d_in[5];
    const float* b2   = (const float*)d_in[6];
    float* out = (float*)d_out;

    const int SMEM_SCORE = 87552;
    cudaFuncSetAttribute(score_topk_kernel,
                         cudaFuncAttributeMaxDynamicSharedMemorySize, SMEM_SCORE);

    zero_kernel<<<8192, 256>>>((float4*)out, out_size / 4);
    compute_v_kernel<<<dim3(64, NMAT, 2), 256>>>(emb1, emb2, w1, w2, b1, b2);
    score_topk_kernel<<<dim3(NSEG, 128), 256, SMEM_SCORE>>>();
    merge_kernel<<<NROWS / 8, 256>>>(out);
}